// round 12
// baseline (speedup 1.0000x reference)
#include <cuda_runtime.h>
#include <stdint.h>

#define NUM_LABELS 100000
#define EMBED      128
#define NTOK       (16 * 4096)

#define BIN_LABELS 32
#define NBINS      (NUM_LABELS / BIN_LABELS)   // 3125, exact — no OOB labels
#define CAP        512                          // slots per bin (mean load ~21)
#define GRID       888                          // 148 SMs x 6 CTAs (smem-limited max)
#define MAX_BPC    4                            // ceil(3125/888)

// __device__ scratch (no cudaMalloc). Zero-initialized at module load;
// fused_kernel resets each cursor after reading it, so every call starts
// from zeros (work is identical on every graph replay).
__device__ int g_cursor[NBINS];
__device__ int g_list[NBINS * CAP];    // packed entries: (token << 5) | local_label

__device__ __forceinline__ uint32_t smem_u32(const void* p) {
    uint32_t a;
    asm("{ .reg .u64 t; cvta.to.shared.u64 t, %1; cvt.u32.u64 %0, t; }" : "=r"(a) : "l"(p));
    return a;
}
__device__ __forceinline__ void cp_async_16(uint32_t dst, const void* src) {
    asm volatile("cp.async.cg.shared.global [%0], [%1], 16;\n"
                 :: "r"(dst), "l"(src) : "memory");
}
__device__ __forceinline__ void cp_async_commit() {
    asm volatile("cp.async.commit_group;\n" ::: "memory");
}
__device__ __forceinline__ void cp_async_wait1() {
    asm volatile("cp.async.wait_group 1;\n" ::: "memory");
}
__device__ __forceinline__ void cp_async_wait0() {
    asm volatile("cp.async.wait_group 0;\n" ::: "memory");
}

// ---------------------------------------------------------------------------
// K1: bin tokens by 32-label range. entry = (token << 5) | (label % 32).
//     int4 X read: 4 tokens per thread. Overflow (pos >= CAP; needs 25x the
//     mean) handled inline so correctness never depends on CAP.
// ---------------------------------------------------------------------------
__global__ __launch_bounds__(256) void bin_kernel(const int* __restrict__ X,
                                                  const float* __restrict__ W,
                                                  const float* __restrict__ bias,
                                                  float* __restrict__ out) {
    const int q = blockIdx.x * 256 + threadIdx.x;   // quad id; grid covers NTOK/4
    const int4 xi = reinterpret_cast<const int4*>(X)[q];
    const int t0 = q * 4;

    int v[4] = {xi.x, xi.y, xi.z, xi.w};
    #pragma unroll
    for (int j = 0; j < 4; j++) {
        int idx = v[j];
        if (idx < 0) idx = 0;
        if (idx >= NUM_LABELS) idx = NUM_LABELS - 1;    // never fault
        const int t   = t0 + j;
        const int bin = idx >> 5;
        const int pos = atomicAdd(&g_cursor[bin], 1);
        if (pos < CAP) {
            g_list[bin * CAP + pos] = (t << 5) | (idx & 31);
        } else {
            // Guaranteed-correct slow path; count == 0 in practice.
            float* o = out + (size_t)t * EMBED;
            for (int e = 0; e < EMBED; e++)
                o[e] = W[(size_t)e * NUM_LABELS + idx] + bias[e];
        }
    }
}

// ---------------------------------------------------------------------------
// K2: persistent, double-buffered fused transpose+scatter+bias (R11 body —
//   measured 24us / DRAM 28% — with ONE change: strided bin assignment so the
//   grid is 888 = 148 x 6 CTAs, restoring full smem-limited occupancy that
//   R11's 625-CTA grid left at 4.2 CTAs/SM).
//
//   CTA c owns bins {c, c+888, c+1776, c+2664} (3-4 bins). Each bin's 16KB
//   tile is prefetched with cp.async.cg 16B while the previous bin scatters.
//
//   Tile layout (e-major, rotation swizzle): phys_word(e,l) = e*32 +
//   ((l + 4*(e&7)) & 31). cp.async src+dst both 16B-contiguous; scatter LDS
//   has a benign 4-way conflict. Stores: scalar STG.32, 128B/warp coalesced.
// ---------------------------------------------------------------------------
__global__ __launch_bounds__(256) void fused_kernel(const float* __restrict__ W,
                                                    const float* __restrict__ bias,
                                                    float* __restrict__ out) {
    __shared__ float tiles[2][EMBED * BIN_LABELS];  // 2 x 16KB
    __shared__ float bs[EMBED];
    __shared__ int   entries[256];
    __shared__ int   s_count[MAX_BPC];

    const int tid = threadIdx.x;
    const int c   = blockIdx.x;

    if (tid < EMBED) bs[tid] = bias[tid];
    if (tid < MAX_BPC) {                            // pre-read owned cursors
        const int b = c + tid * GRID;
        if (b < NBINS) {
            s_count[tid] = g_cursor[b];
            g_cursor[b] = 0;                        // reset for next replay
        }
    }

    // Per-thread prefetch mapping: 2 threads per e-row, 4 x 16B chunks each.
    const int pe = tid >> 1;                        // 0..127
    const int ps = pe & 7;                          // rotation for this e-row
    const int p0 = (tid & 1) * 4;
    const float* wrow = W + (size_t)pe * NUM_LABELS;
    float* drow[2] = { &tiles[0][pe * BIN_LABELS], &tiles[1][pe * BIN_LABELS] };

    // Prime: prefetch first bin into buffer 0.
    {
        const int l0 = c * BIN_LABELS;
        #pragma unroll
        for (int k = 0; k < 4; k++) {
            const int p = p0 + k;
            const int soff = 4 * ((p - ps) & 7);
            cp_async_16(smem_u32(drow[0] + 4 * p), wrow + l0 + soff);
        }
        cp_async_commit();
    }

    const int warp = tid >> 5;
    const int lane = tid & 31;

    int bin = c;
    for (int j = 0; bin < NBINS; j++, bin += GRID) {
        const int cur  = j & 1;
        const int nbin = bin + GRID;

        if (nbin < NBINS) {
            const int l1 = nbin * BIN_LABELS;
            float* dn = drow[cur ^ 1];
            #pragma unroll
            for (int k = 0; k < 4; k++) {
                const int p = p0 + k;
                const int soff = 4 * ((p - ps) & 7);
                cp_async_16(smem_u32(dn + 4 * p), wrow + l1 + soff);
            }
            cp_async_commit();
            cp_async_wait1();                       // current bin's group done
        } else {
            cp_async_wait0();
        }
        __syncthreads();                            // tile[cur] + s_count visible

        int count = s_count[j];
        if (count > CAP) count = CAP;
        const float* tile = tiles[cur];

        for (int base = 0; base < count; base += 256) {
            const int n = min(256, count - base);
            if (tid < n) entries[tid] = g_list[bin * CAP + base + tid];
            __syncthreads();

            for (int i = warp; i < n; i += 8) {     // one warp per token
                const int ent = entries[i];
                const int tok = ent >> 5;
                const int lab = ent & 31;
                float* o = out + (size_t)tok * EMBED;
                #pragma unroll
                for (int k = 0; k < 4; k++) {
                    const int e = lane + 32 * k;
                    const float v = tile[e * BIN_LABELS + ((lab + 4 * (e & 7)) & 31)];
                    o[e] = v + bs[e];
                }
            }
            __syncthreads();                        // entries + tile[cur] reusable
        }
    }
}

// ---------------------------------------------------------------------------
// Launch (2 kernels). Inputs identified by element count:
//   65536 -> X (int32), 12800000 -> W (f32 [EMBED,NUM_LABELS]), 128 -> b
// ---------------------------------------------------------------------------
extern "C" void kernel_launch(void* const* d_in, const int* in_sizes, int n_in,
                              void* d_out, int out_size) {
    const int*   X = nullptr;
    const float* W = nullptr;
    const float* b = nullptr;

    for (int i = 0; i < n_in; i++) {
        if (in_sizes[i] == NTOK)                    X = (const int*)d_in[i];
        else if (in_sizes[i] == EMBED * NUM_LABELS) W = (const float*)d_in[i];
        else if (in_sizes[i] == EMBED)              b = (const float*)d_in[i];
    }
    if (!X) X = (const int*)d_in[0];
    if (!W) W = (const float*)d_in[1];
    if (!b) b = (const float*)d_in[2];

    float* out = (float*)d_out;

    bin_kernel<<<NTOK / 1024, 256>>>(X, W, b, out);   // 4 tokens/thread
    fused_kernel<<<GRID, 256>>>(W, b, out);
}

// round 13
// speedup vs baseline: 1.5279x; 1.5279x over previous
#include <cuda_runtime.h>
#include <stdint.h>

#define NUM_LABELS 100000
#define EMBED      128
#define NTOK       (16 * 4096)

#define BIN_LABELS 32
#define NBINS      (NUM_LABELS / BIN_LABELS)     // 3125, exact
#define CAP        512                            // slots per bin (mean load ~21)
#define BPC        6                              // bins per CTA (blocked)
#define GRID       ((NBINS + BPC - 1) / BPC)      // 521 CTAs, single wave @4/SM
#define TILE_WORDS (EMBED * BIN_LABELS)           // 4096 floats = 16KB
#define NSTAGE     3
#define SMEM_BYTES (NSTAGE * TILE_WORDS * 4 + NSTAGE * CAP * 4)   // 55296

// __device__ scratch (no cudaMalloc). Zero-initialized at module load;
// fused_kernel resets cursors after reading them, so every call starts
// from zeros (identical work on every graph replay).
__device__ int g_cursor[NBINS];
__device__ int g_list[NBINS * CAP];    // packed: (token << 5) | local_label

__device__ __forceinline__ uint32_t smem_u32(const void* p) {
    uint32_t a;
    asm("{ .reg .u64 t; cvta.to.shared.u64 t, %1; cvt.u32.u64 %0, t; }" : "=r"(a) : "l"(p));
    return a;
}
__device__ __forceinline__ void cp_async_16(uint32_t dst, const void* src) {
    asm volatile("cp.async.cg.shared.global [%0], [%1], 16;\n" :: "r"(dst), "l"(src) : "memory");
}
__device__ __forceinline__ void cp_async_4(uint32_t dst, const void* src) {
    asm volatile("cp.async.ca.shared.global [%0], [%1], 4;\n" :: "r"(dst), "l"(src) : "memory");
}
__device__ __forceinline__ void cp_async_commit() {
    asm volatile("cp.async.commit_group;\n" ::: "memory");
}
__device__ __forceinline__ void cp_async_wait2() { asm volatile("cp.async.wait_group 2;\n" ::: "memory"); }
__device__ __forceinline__ void cp_async_wait1() { asm volatile("cp.async.wait_group 1;\n" ::: "memory"); }
__device__ __forceinline__ void cp_async_wait0() { asm volatile("cp.async.wait_group 0;\n" ::: "memory"); }

// ---------------------------------------------------------------------------
// K1: bin tokens by 32-label range. entry = (token << 5) | (label % 32).
//     int4 X reads (4 tokens/thread). Overflow (pos >= CAP, needs 25x mean —
//     impossible here) handled inline: correctness never depends on CAP.
// ---------------------------------------------------------------------------
__global__ __launch_bounds__(256) void bin_kernel(const int* __restrict__ X,
                                                  const float* __restrict__ W,
                                                  const float* __restrict__ bias,
                                                  float* __restrict__ out) {
    const int q = blockIdx.x * 256 + threadIdx.x;   // quad id; grid covers NTOK/4
    const int4 xi = reinterpret_cast<const int4*>(X)[q];
    const int t0 = q * 4;

    int v[4] = {xi.x, xi.y, xi.z, xi.w};
    #pragma unroll
    for (int j = 0; j < 4; j++) {
        int idx = v[j];
        if (idx < 0) idx = 0;
        if (idx >= NUM_LABELS) idx = NUM_LABELS - 1;
        const int t   = t0 + j;
        const int bin = idx >> 5;
        const int pos = atomicAdd(&g_cursor[bin], 1);
        if (pos < CAP) {
            g_list[bin * CAP + pos] = (t << 5) | (idx & 31);
        } else {
            float* o = out + (size_t)t * EMBED;     // guaranteed-correct slow path
            for (int e = 0; e < EMBED; e++)
                o[e] = W[(size_t)e * NUM_LABELS + idx] + bias[e];
        }
    }
}

// ---------------------------------------------------------------------------
// K2: persistent, 3-stage-pipelined fused transpose + scatter + bias.
//   CTA c owns blocked bins [6c, 6c+6). While bin j scatters, bins j+1 and
//   j+2 (tiles AND their entry lists) are in flight via cp.async — 32KB of
//   per-CTA outstanding loads (2x R11, the lever that measurably worked).
//
//   Tile layout (e-major, rotation swizzle, validated R11/R12):
//     phys_word(e,l) = e*32 + ((l + 4*(e&7)) & 31)
//   cp.async src+dst both 16B-contiguous; scatter LDS has a benign 4-way
//   conflict. Stores: scalar STG.32, 128B coalesced per warp, 512B/token.
//   Entries live in SMEM (cp.async'd with the tile): scatter's per-token
//   pointer chase is a 29cyc LDS broadcast, not a 230cyc L2 load.
// ---------------------------------------------------------------------------
__global__ __launch_bounds__(256) void fused_kernel(const float* __restrict__ W,
                                                    const float* __restrict__ bias,
                                                    float* __restrict__ out) {
    extern __shared__ float dsm[];
    float* tiles = dsm;                               // [3][TILE_WORDS]
    int*   ents  = (int*)(dsm + NSTAGE * TILE_WORDS); // [3][CAP]

    const int tid  = threadIdx.x;
    const int lane = tid & 31;
    const int warp = tid >> 5;
    const int bin0 = blockIdx.x * BPC;
    const int nb   = min(BPC, NBINS - bin0);          // 6 (last CTA: 5)

    // Bias in registers (coalesced 128B/warp, L1-cached).
    const float bb0 = bias[lane];
    const float bb1 = bias[lane + 32];
    const float bb2 = bias[lane + 64];
    const float bb3 = bias[lane + 96];

    // All threads read all owned counts (broadcast loads) BEFORE any reset.
    int rcount[BPC];
    #pragma unroll
    for (int k = 0; k < BPC; k++)
        rcount[k] = (k < nb) ? g_cursor[bin0 + k] : 0;
    __syncthreads();
    if (tid < nb) g_cursor[bin0 + tid] = 0;           // reset for next replay
    #pragma unroll
    for (int k = 0; k < BPC; k++)
        if (rcount[k] > CAP) rcount[k] = CAP;

    // Prefetch mapping: 2 threads per e-row, 4 x 16B chunks each.
    const int pe = tid >> 1;                          // 0..127
    const int ps = pe & 7;
    const int p0 = (tid & 1) * 4;
    const float* wrow = W + (size_t)pe * NUM_LABELS;

    auto prefetch = [&](int j) {
        const int buf = j % NSTAGE;
        const int bin = bin0 + j;
        float* dst = tiles + buf * TILE_WORDS + pe * BIN_LABELS;
        const int l0 = bin * BIN_LABELS;
        #pragma unroll
        for (int k = 0; k < 4; k++) {
            const int p = p0 + k;
            const int soff = 4 * ((p - ps) & 7);
            cp_async_16(smem_u32(dst + 4 * p), wrow + l0 + soff);
        }
        const int cnt = rcount[j];
        for (int t = tid; t < cnt; t += 256)
            cp_async_4(smem_u32(&ents[buf * CAP + t]), &g_list[bin * CAP + t]);
        cp_async_commit();
    };

    // Prime two stages (nb >= 5 always).
    prefetch(0);
    prefetch(1);

    for (int j = 0; j < nb; j++) {
        // Keep 2 stages ahead; wait until group j is complete.
        if (j + 2 < nb)      { prefetch(j + 2); cp_async_wait2(); }
        else if (j + 1 < nb) { cp_async_wait1(); }
        else                 { cp_async_wait0(); }
        __syncthreads();                              // tile+ents[j%3] visible

        const int cnt = rcount[j];
        const float* tile = tiles + (j % NSTAGE) * TILE_WORDS;
        const int*   eb   = ents  + (j % NSTAGE) * CAP;

        for (int i = warp; i < cnt; i += 8) {         // one warp per token
            const int ent = eb[i];                    // LDS broadcast
            const int tok = ent >> 5;
            const int lab = ent & 31;
            const int lw  = (lab + 4 * (lane & 7)) & 31;   // swizzle, same all k
            float* o = out + (size_t)tok * EMBED;
            o[lane]      = tile[lane * 32 + lw]        + bb0;
            o[lane + 32] = tile[(lane + 32) * 32 + lw] + bb1;
            o[lane + 64] = tile[(lane + 64) * 32 + lw] + bb2;
            o[lane + 96] = tile[(lane + 96) * 32 + lw] + bb3;
        }
        __syncthreads();                              // buf[j%3] reusable at j+1's prefetch
    }
}

// ---------------------------------------------------------------------------
// Launch (2 kernels). Inputs identified by element count:
//   65536 -> X (int32), 12800000 -> W (f32 [EMBED,NUM_LABELS]), 128 -> b
// ---------------------------------------------------------------------------
extern "C" void kernel_launch(void* const* d_in, const int* in_sizes, int n_in,
                              void* d_out, int out_size) {
    const int*   X = nullptr;
    const float* W = nullptr;
    const float* b = nullptr;

    for (int i = 0; i < n_in; i++) {
        if (in_sizes[i] == NTOK)                    X = (const int*)d_in[i];
        else if (in_sizes[i] == EMBED * NUM_LABELS) W = (const float*)d_in[i];
        else if (in_sizes[i] == EMBED)              b = (const float*)d_in[i];
    }
    if (!X) X = (const int*)d_in[0];
    if (!W) W = (const float*)d_in[1];
    if (!b) b = (const float*)d_in[2];

    float* out = (float*)d_out;

    // Host-side attribute set (idempotent, not a stream op — capture-safe).
    cudaFuncSetAttribute(fused_kernel,
                         cudaFuncAttributeMaxDynamicSharedMemorySize, SMEM_BYTES);

    bin_kernel<<<NTOK / 1024, 256>>>(X, W, b, out);   // 4 tokens/thread
    fused_kernel<<<GRID, 256, SMEM_BYTES>>>(W, b, out);
}